// round 1
// baseline (speedup 1.0000x reference)
#include <cuda_runtime.h>
#include <math.h>

// ---------------------------------------------------------------------------
// ReDrafterHead: 2-layer GRU draft head + big vocab projection.
// B=64, HIDDEN=4096, DH=512, VOCAB=50257, NUM_DRAFT=4.
//
// Plan:
//   h0 = hidden @ ip_w.T + ip_b            (split-K tiled SGEMM + reduce)
//   4 sequential steps:
//     gates = [x@w_ih.T | h@w_hh.T]        (split-K tiled SGEMM, gi/gh kept separate)
//     GRU combine (elementwise)            -> new h; layer1 h2 stored at row b*4+step
//     x = embed[target_ids[:,step]]        (gather)
//   logits[256,50257] = h2_all @ out_w.T   (one tiled SGEMM, writes d_out directly)
// ---------------------------------------------------------------------------

#define B_      64
#define HID     4096
#define DH      512
#define VOCAB   50257
#define NDRAFT  4
#define G3      1536   // 3*DH

// scratch (device globals; allocation in kernel_launch is forbidden)
__device__ float g_hA[B_ * DH];            // layer-0 hidden state
__device__ float g_hB[B_ * DH];            // layer-1 hidden state
__device__ float g_x[B_ * DH];             // GRU input
__device__ float g_h2all[B_ * NDRAFT * DH];// h2 rows, m = b*4+step
__device__ float g_part[4 * B_ * 2 * G3];  // split-K partials (786432 floats, covers all uses)

__device__ __forceinline__ float sigmoidf_(float v) { return 1.0f / (1.0f + __expf(-v)); }

// ---------------------------------------------------------------------------
// Kernel 1: input projection split-K GEMM.
// partial[s][m][n] = sum_{k in slice s} hidden[m,k] * ip_w[n,k]
// M=64, N=512, K=4096, SPLIT=8 (slice 512). grid (8 n-tiles, 8 splits), 256 thr.
// BM=64, BN=64, BK=32, uT 4x4.
// ---------------------------------------------------------------------------
__global__ __launch_bounds__(256) void ip_gemm(const float* __restrict__ A,
                                               const float* __restrict__ W)
{
    __shared__ float As[32][64];
    __shared__ float Ws[32][64];
    const int n0 = blockIdx.x * 64;
    const int kbase = blockIdx.y * 512;
    const int tid = threadIdx.x;
    const int ty = tid >> 4;   // 0..15
    const int tx = tid & 15;   // 0..15

    float acc[4][4] = {};

    for (int kt = 0; kt < 512; kt += 32) {
        #pragma unroll
        for (int i = 0; i < 2; i++) {
            int f = tid + i * 256;          // 0..511
            int m = f >> 3;                 // 0..63
            int kq = (f & 7) << 2;          // 0,4,...,28
            float4 va = *reinterpret_cast<const float4*>(&A[m * HID + kbase + kt + kq]);
            As[kq + 0][m] = va.x; As[kq + 1][m] = va.y; As[kq + 2][m] = va.z; As[kq + 3][m] = va.w;
            float4 vw = *reinterpret_cast<const float4*>(&W[(n0 + m) * HID + kbase + kt + kq]);
            Ws[kq + 0][m] = vw.x; Ws[kq + 1][m] = vw.y; Ws[kq + 2][m] = vw.z; Ws[kq + 3][m] = vw.w;
        }
        __syncthreads();
        #pragma unroll
        for (int kk = 0; kk < 32; kk++) {
            float a[4], b[4];
            #pragma unroll
            for (int i = 0; i < 4; i++) { a[i] = As[kk][ty * 4 + i]; b[i] = Ws[kk][tx * 4 + i]; }
            #pragma unroll
            for (int i = 0; i < 4; i++)
                #pragma unroll
                for (int j = 0; j < 4; j++) acc[i][j] += a[i] * b[j];
        }
        __syncthreads();
    }

    float* part = g_part + blockIdx.y * (B_ * DH);
    #pragma unroll
    for (int i = 0; i < 4; i++)
        #pragma unroll
        for (int j = 0; j < 4; j++)
            part[(ty * 4 + i) * DH + n0 + tx * 4 + j] = acc[i][j];
}

// reduce 8 split-K partials + bias; init both GRU states and x=0
__global__ void ip_reduce(const float* __restrict__ ip_b)
{
    int idx = blockIdx.x * blockDim.x + threadIdx.x;
    if (idx >= B_ * DH) return;
    float s = 0.f;
    #pragma unroll
    for (int p = 0; p < 8; p++) s += g_part[p * (B_ * DH) + idx];
    s += ip_b[idx & (DH - 1)];
    g_hA[idx] = s;
    g_hB[idx] = s;
    g_x[idx]  = 0.f;
}

// ---------------------------------------------------------------------------
// Kernel 2: GRU gate GEMMs. Two independent GEMMs (gi = x@w_ih.T, gh = h@w_hh.T)
// packed along grid.x: n-tiles 0..23 -> gi, 24..47 -> gh. split-K=4 (slice 128).
// partial layout: part[s][m][3072] with gi at cols [0,1536), gh at [1536,3072).
// ---------------------------------------------------------------------------
__global__ __launch_bounds__(256) void gates_gemm(const float* __restrict__ w_ih,
                                                  const float* __restrict__ w_hh,
                                                  int layer)
{
    __shared__ float As[32][64];
    __shared__ float Ws[32][64];
    const bool is_gh = blockIdx.x >= 24;
    const int  nb    = (is_gh ? blockIdx.x - 24 : blockIdx.x) * 64;  // 0..1472
    const int  kbase = blockIdx.y * 128;
    const float* A = (layer == 0) ? (is_gh ? g_hA : g_x) : (is_gh ? g_hB : g_hA);
    const float* W = is_gh ? w_hh : w_ih;

    const int tid = threadIdx.x;
    const int ty = tid >> 4;
    const int tx = tid & 15;

    float acc[4][4] = {};

    for (int kt = 0; kt < 128; kt += 32) {
        #pragma unroll
        for (int i = 0; i < 2; i++) {
            int f = tid + i * 256;
            int m = f >> 3;
            int kq = (f & 7) << 2;
            float4 va = *reinterpret_cast<const float4*>(&A[m * DH + kbase + kt + kq]);
            As[kq + 0][m] = va.x; As[kq + 1][m] = va.y; As[kq + 2][m] = va.z; As[kq + 3][m] = va.w;
            float4 vw = *reinterpret_cast<const float4*>(&W[(nb + m) * DH + kbase + kt + kq]);
            Ws[kq + 0][m] = vw.x; Ws[kq + 1][m] = vw.y; Ws[kq + 2][m] = vw.z; Ws[kq + 3][m] = vw.w;
        }
        __syncthreads();
        #pragma unroll
        for (int kk = 0; kk < 32; kk++) {
            float a[4], b[4];
            #pragma unroll
            for (int i = 0; i < 4; i++) { a[i] = As[kk][ty * 4 + i]; b[i] = Ws[kk][tx * 4 + i]; }
            #pragma unroll
            for (int i = 0; i < 4; i++)
                #pragma unroll
                for (int j = 0; j < 4; j++) acc[i][j] += a[i] * b[j];
        }
        __syncthreads();
    }

    float* part = g_part + blockIdx.y * (B_ * 2 * G3) + (is_gh ? G3 : 0);
    #pragma unroll
    for (int i = 0; i < 4; i++)
        #pragma unroll
        for (int j = 0; j < 4; j++)
            part[(ty * 4 + i) * (2 * G3) + nb + tx * 4 + j] = acc[i][j];
}

// GRU elementwise combine. layer selects which state buffer to update.
// layer 1 additionally stores h2 into g_h2all at row b*4+step.
__global__ void gru_combine(const float* __restrict__ b_ih,
                            const float* __restrict__ b_hh,
                            int layer, int step)
{
    int idx = blockIdx.x * blockDim.x + threadIdx.x;
    if (idx >= B_ * DH) return;
    int b = idx >> 9;          // /512
    int j = idx & (DH - 1);

    float gir = 0.f, giz = 0.f, gin = 0.f, ghr = 0.f, ghz = 0.f, ghn = 0.f;
    #pragma unroll
    for (int s = 0; s < 4; s++) {
        const float* p = g_part + s * (B_ * 2 * G3) + b * (2 * G3);
        gir += p[j];            giz += p[512 + j];        gin += p[1024 + j];
        ghr += p[1536 + j];     ghz += p[2048 + j];       ghn += p[2560 + j];
    }
    float r = sigmoidf_(gir + b_ih[j]        + ghr + b_hh[j]);
    float z = sigmoidf_(giz + b_ih[512 + j]  + ghz + b_hh[512 + j]);
    float n = tanhf(gin + b_ih[1024 + j] + r * (ghn + b_hh[1024 + j]));

    float* h = (layer == 0) ? g_hA : g_hB;
    float hold = h[idx];
    float hnew = (1.f - z) * n + z * hold;
    h[idx] = hnew;
    if (layer == 1) g_h2all[(b * NDRAFT + step) * DH + j] = hnew;
}

// x = embed[target_ids[:, step]]
__global__ void gather_x(const float* __restrict__ embed,
                         const int* __restrict__ tids, int step)
{
    int idx = blockIdx.x * blockDim.x + threadIdx.x;
    if (idx >= B_ * DH) return;
    int b = idx >> 9;
    int j = idx & (DH - 1);
    long row = (long)tids[b * NDRAFT + step];
    g_x[idx] = embed[row * DH + j];
}

// ---------------------------------------------------------------------------
// Kernel 3: logits GEMM. C[m][v] = sum_k g_h2all[m][k] * out_w[v][k]
// M=256, N=50257, K=512. BM=64, BN=128, BK=16, 256 thr, uT 8x4.
// grid (ceil(50257/128)=393, 4). Writes d_out directly (m = b*4+step layout).
// ---------------------------------------------------------------------------
__global__ __launch_bounds__(256) void logits_gemm(const float* __restrict__ W,
                                                   float* __restrict__ out)
{
    __shared__ float As[16][64];
    __shared__ float Ws[16][128];
    const int n0 = blockIdx.x * 128;
    const int m0 = blockIdx.y * 64;
    const int tid = threadIdx.x;
    const int ty = tid >> 5;   // 0..7
    const int tx = tid & 31;   // 0..31

    float acc[8][4] = {};

    for (int kt = 0; kt < 512; kt += 16) {
        // A tile: 64x16 = 256 float4, one per thread
        {
            int m = tid >> 2;
            int kq = (tid & 3) << 2;
            float4 v = *reinterpret_cast<const float4*>(&g_h2all[(m0 + m) * DH + kt + kq]);
            As[kq + 0][m] = v.x; As[kq + 1][m] = v.y; As[kq + 2][m] = v.z; As[kq + 3][m] = v.w;
        }
        // W tile: 128x16 = 512 float4, two per thread (row-bounds checked)
        #pragma unroll
        for (int i = 0; i < 2; i++) {
            int f = tid + i * 256;
            int n = f >> 2;
            int kq = (f & 3) << 2;
            int vrow = n0 + n;
            float4 v = make_float4(0.f, 0.f, 0.f, 0.f);
            if (vrow < VOCAB)
                v = *reinterpret_cast<const float4*>(&W[(long)vrow * DH + kt + kq]);
            Ws[kq + 0][n] = v.x; Ws[kq + 1][n] = v.y; Ws[kq + 2][n] = v.z; Ws[kq + 3][n] = v.w;
        }
        __syncthreads();
        #pragma unroll
        for (int kk = 0; kk < 16; kk++) {
            float a[8], b[4];
            *reinterpret_cast<float4*>(&a[0]) = *reinterpret_cast<const float4*>(&As[kk][ty * 8]);
            *reinterpret_cast<float4*>(&a[4]) = *reinterpret_cast<const float4*>(&As[kk][ty * 8 + 4]);
            *reinterpret_cast<float4*>(&b[0]) = *reinterpret_cast<const float4*>(&Ws[kk][tx * 4]);
            #pragma unroll
            for (int i = 0; i < 8; i++)
                #pragma unroll
                for (int j = 0; j < 4; j++) acc[i][j] += a[i] * b[j];
        }
        __syncthreads();
    }

    // scalar stores: VOCAB=50257 is odd, rows are not 16B aligned
    #pragma unroll
    for (int i = 0; i < 8; i++) {
        int m = m0 + ty * 8 + i;
        long rowbase = (long)m * VOCAB;
        #pragma unroll
        for (int j = 0; j < 4; j++) {
            int v = n0 + tx * 4 + j;
            if (v < VOCAB) out[rowbase + v] = acc[i][j];
        }
    }
}

// ---------------------------------------------------------------------------
extern "C" void kernel_launch(void* const* d_in, const int* in_sizes, int n_in,
                              void* d_out, int out_size)
{
    const float* hidden = (const float*)d_in[0];
    const int*   tids   = (const int*)  d_in[1];
    const float* ip_w   = (const float*)d_in[2];
    const float* ip_b   = (const float*)d_in[3];
    const float* w_ih0  = (const float*)d_in[4];
    const float* w_hh0  = (const float*)d_in[5];
    const float* b_ih0  = (const float*)d_in[6];
    const float* b_hh0  = (const float*)d_in[7];
    const float* w_ih1  = (const float*)d_in[8];
    const float* w_hh1  = (const float*)d_in[9];
    const float* b_ih1  = (const float*)d_in[10];
    const float* b_hh1  = (const float*)d_in[11];
    const float* embed  = (const float*)d_in[12];
    const float* out_w  = (const float*)d_in[13];
    float* out = (float*)d_out;

    // input projection -> h0 (both layer states), x = 0
    ip_gemm<<<dim3(8, 8), 256>>>(hidden, ip_w);
    ip_reduce<<<128, 256>>>(ip_b);

    for (int step = 0; step < NDRAFT; step++) {
        // layer 0
        gates_gemm<<<dim3(48, 4), 256>>>(w_ih0, w_hh0, 0);
        gru_combine<<<128, 256>>>(b_ih0, b_hh0, 0, step);
        // layer 1
        gates_gemm<<<dim3(48, 4), 256>>>(w_ih1, w_hh1, 1);
        gru_combine<<<128, 256>>>(b_ih1, b_hh1, 1, step);
        // next input
        if (step < NDRAFT - 1) gather_x<<<128, 256>>>(embed, tids, step);
    }

    // batched vocab projection over all 4 steps, writes output directly
    logits_gemm<<<dim3((VOCAB + 127) / 128, 4), 256>>>(out_w, out);
}

// round 4
// speedup vs baseline: 1.5130x; 1.5130x over previous
#include <cuda_runtime.h>
#include <cuda_bf16.h>
#include <math.h>
#include <stdint.h>

// ---------------------------------------------------------------------------
// ReDrafterHead: 2-layer GRU draft head + big vocab projection.
// B=64, HIDDEN=4096, DH=512, VOCAB=50257, NUM_DRAFT=4.
//
// Round 4: toolchain targets .target sm_103 (no 'a') -> tcgen05 unavailable.
// Logits GEMM via mma.sync m16n8k16 bf16 (baseline PTX, HMMA path),
// bf16 hi/lo 3-MMA split for fp32-class accuracy.
// ---------------------------------------------------------------------------

#define B_      64
#define HID     4096
#define DH      512
#define VOCAB   50257
#define NDRAFT  4
#define G3      1536   // 3*DH

// scratch (device globals; allocation in kernel_launch is forbidden)
__device__ float g_hA[B_ * DH];
__device__ float g_hB[B_ * DH];
__device__ float g_x[B_ * DH];
__device__ float g_h2all[B_ * NDRAFT * DH];
__device__ float g_part[4 * B_ * 2 * G3];
__device__ __nv_bfloat16 g_Ahi[B_ * NDRAFT * DH];
__device__ __nv_bfloat16 g_Alo[B_ * NDRAFT * DH];

__device__ __forceinline__ float sigmoidf_(float v) { return 1.0f / (1.0f + __expf(-v)); }

__device__ __forceinline__ uint32_t pack_bf16x2(__nv_bfloat16 lo, __nv_bfloat16 hi) {
    return ((uint32_t)__bfloat16_as_ushort(hi) << 16) | (uint32_t)__bfloat16_as_ushort(lo);
}
__device__ __forceinline__ uint32_t smem_to_u32(const void* p) {
    uint32_t a;
    asm("{ .reg .u64 t; cvta.to.shared.u64 t, %1; cvt.u32.u64 %0, t; }" : "=r"(a) : "l"(p));
    return a;
}
__device__ __forceinline__ void ldsm4(uint32_t* r, uint32_t addr) {
    asm volatile("ldmatrix.sync.aligned.m8n8.x4.shared.b16 {%0,%1,%2,%3}, [%4];"
        : "=r"(r[0]), "=r"(r[1]), "=r"(r[2]), "=r"(r[3]) : "r"(addr));
}
__device__ __forceinline__ void mma16816(float* d, const uint32_t* a, const uint32_t* b) {
    asm volatile("mma.sync.aligned.m16n8k16.row.col.f32.bf16.bf16.f32 "
        "{%0,%1,%2,%3}, {%4,%5,%6,%7}, {%8,%9}, {%0,%1,%2,%3};"
        : "+f"(d[0]), "+f"(d[1]), "+f"(d[2]), "+f"(d[3])
        : "r"(a[0]), "r"(a[1]), "r"(a[2]), "r"(a[3]), "r"(b[0]), "r"(b[1]));
}

// ---------------------------------------------------------------------------
// Kernel 1: input projection split-K GEMM (proven round 1).
// ---------------------------------------------------------------------------
__global__ __launch_bounds__(256) void ip_gemm(const float* __restrict__ A,
                                               const float* __restrict__ W)
{
    __shared__ float As[32][64];
    __shared__ float Ws[32][64];
    const int n0 = blockIdx.x * 64;
    const int kbase = blockIdx.y * 512;
    const int tid = threadIdx.x;
    const int ty = tid >> 4;
    const int tx = tid & 15;

    float acc[4][4] = {};

    for (int kt = 0; kt < 512; kt += 32) {
        #pragma unroll
        for (int i = 0; i < 2; i++) {
            int f = tid + i * 256;
            int m = f >> 3;
            int kq = (f & 7) << 2;
            float4 va = *reinterpret_cast<const float4*>(&A[m * HID + kbase + kt + kq]);
            As[kq + 0][m] = va.x; As[kq + 1][m] = va.y; As[kq + 2][m] = va.z; As[kq + 3][m] = va.w;
            float4 vw = *reinterpret_cast<const float4*>(&W[(n0 + m) * HID + kbase + kt + kq]);
            Ws[kq + 0][m] = vw.x; Ws[kq + 1][m] = vw.y; Ws[kq + 2][m] = vw.z; Ws[kq + 3][m] = vw.w;
        }
        __syncthreads();
        #pragma unroll
        for (int kk = 0; kk < 32; kk++) {
            float a[4], b[4];
            #pragma unroll
            for (int i = 0; i < 4; i++) { a[i] = As[kk][ty * 4 + i]; b[i] = Ws[kk][tx * 4 + i]; }
            #pragma unroll
            for (int i = 0; i < 4; i++)
                #pragma unroll
                for (int j = 0; j < 4; j++) acc[i][j] += a[i] * b[j];
        }
        __syncthreads();
    }

    float* part = g_part + blockIdx.y * (B_ * DH);
    #pragma unroll
    for (int i = 0; i < 4; i++)
        #pragma unroll
        for (int j = 0; j < 4; j++)
            part[(ty * 4 + i) * DH + n0 + tx * 4 + j] = acc[i][j];
}

__global__ void ip_reduce(const float* __restrict__ ip_b)
{
    int idx = blockIdx.x * blockDim.x + threadIdx.x;
    if (idx >= B_ * DH) return;
    float s = 0.f;
    #pragma unroll
    for (int p = 0; p < 8; p++) s += g_part[p * (B_ * DH) + idx];
    s += ip_b[idx & (DH - 1)];
    g_hA[idx] = s;
    g_hB[idx] = s;
    g_x[idx]  = 0.f;
}

// ---------------------------------------------------------------------------
// Kernel 2: GRU gate GEMMs (proven round 1).
// ---------------------------------------------------------------------------
__global__ __launch_bounds__(256) void gates_gemm(const float* __restrict__ w_ih,
                                                  const float* __restrict__ w_hh,
                                                  int layer)
{
    __shared__ float As[32][64];
    __shared__ float Ws[32][64];
    const bool is_gh = blockIdx.x >= 24;
    const int  nb    = (is_gh ? blockIdx.x - 24 : blockIdx.x) * 64;
    const int  kbase = blockIdx.y * 128;
    const float* A = (layer == 0) ? (is_gh ? g_hA : g_x) : (is_gh ? g_hB : g_hA);
    const float* W = is_gh ? w_hh : w_ih;

    const int tid = threadIdx.x;
    const int ty = tid >> 4;
    const int tx = tid & 15;

    float acc[4][4] = {};

    for (int kt = 0; kt < 128; kt += 32) {
        #pragma unroll
        for (int i = 0; i < 2; i++) {
            int f = tid + i * 256;
            int m = f >> 3;
            int kq = (f & 7) << 2;
            float4 va = *reinterpret_cast<const float4*>(&A[m * DH + kbase + kt + kq]);
            As[kq + 0][m] = va.x; As[kq + 1][m] = va.y; As[kq + 2][m] = va.z; As[kq + 3][m] = va.w;
            float4 vw = *reinterpret_cast<const float4*>(&W[(nb + m) * DH + kbase + kt + kq]);
            Ws[kq + 0][m] = vw.x; Ws[kq + 1][m] = vw.y; Ws[kq + 2][m] = vw.z; Ws[kq + 3][m] = vw.w;
        }
        __syncthreads();
        #pragma unroll
        for (int kk = 0; kk < 32; kk++) {
            float a[4], b[4];
            #pragma unroll
            for (int i = 0; i < 4; i++) { a[i] = As[kk][ty * 4 + i]; b[i] = Ws[kk][tx * 4 + i]; }
            #pragma unroll
            for (int i = 0; i < 4; i++)
                #pragma unroll
                for (int j = 0; j < 4; j++) acc[i][j] += a[i] * b[j];
        }
        __syncthreads();
    }

    float* part = g_part + blockIdx.y * (B_ * 2 * G3) + (is_gh ? G3 : 0);
    #pragma unroll
    for (int i = 0; i < 4; i++)
        #pragma unroll
        for (int j = 0; j < 4; j++)
            part[(ty * 4 + i) * (2 * G3) + nb + tx * 4 + j] = acc[i][j];
}

__global__ void gru_combine(const float* __restrict__ b_ih,
                            const float* __restrict__ b_hh,
                            int layer, int step)
{
    int idx = blockIdx.x * blockDim.x + threadIdx.x;
    if (idx >= B_ * DH) return;
    int b = idx >> 9;
    int j = idx & (DH - 1);

    float gir = 0.f, giz = 0.f, gin = 0.f, ghr = 0.f, ghz = 0.f, ghn = 0.f;
    #pragma unroll
    for (int s = 0; s < 4; s++) {
        const float* p = g_part + s * (B_ * 2 * G3) + b * (2 * G3);
        gir += p[j];            giz += p[512 + j];        gin += p[1024 + j];
        ghr += p[1536 + j];     ghz += p[2048 + j];       ghn += p[2560 + j];
    }
    float r = sigmoidf_(gir + b_ih[j]        + ghr + b_hh[j]);
    float z = sigmoidf_(giz + b_ih[512 + j]  + ghz + b_hh[512 + j]);
    float n = tanhf(gin + b_ih[1024 + j] + r * (ghn + b_hh[1024 + j]));

    float* h = (layer == 0) ? g_hA : g_hB;
    float hold = h[idx];
    float hnew = (1.f - z) * n + z * hold;
    h[idx] = hnew;
    if (layer == 1) g_h2all[(b * NDRAFT + step) * DH + j] = hnew;
}

__global__ void gather_x(const float* __restrict__ embed,
                         const int* __restrict__ tids, int step)
{
    int idx = blockIdx.x * blockDim.x + threadIdx.x;
    if (idx >= B_ * DH) return;
    int b = idx >> 9;
    int j = idx & (DH - 1);
    long row = (long)tids[b * NDRAFT + step];
    g_x[idx] = embed[row * DH + j];
}

// ---------------------------------------------------------------------------
// A conversion: g_h2all (fp32 256x512) -> bf16 hi/lo.
// ---------------------------------------------------------------------------
__global__ void a_convert()
{
    int idx = blockIdx.x * blockDim.x + threadIdx.x;
    if (idx >= B_ * NDRAFT * DH) return;
    float v = g_h2all[idx];
    __nv_bfloat16 hi = __float2bfloat16(v);
    float r = v - __bfloat162float(hi);
    g_Ahi[idx] = hi;
    g_Alo[idx] = __float2bfloat16(r);
}

// ---------------------------------------------------------------------------
// Kernel 3: logits GEMM via mma.sync (bf16 hi/lo 3-MMA split, fp32 accum).
// out[m, v] = sum_k h2[m,k] * out_w[v,k].  M=256, N=50257, K=512.
// CTA tile 128x128x32, 8 warps (2 M x 4 N), warp tile 64x32.
// SMEM rows padded to 80B: conflict-free ldmatrix + aligned cp.async.
// ---------------------------------------------------------------------------
#define ROWB 80
#define AHI_OFF(s) ((s) * 10240)
#define ALO_OFF(s) (20480 + (s) * 10240)
#define BHI_OFF(s) (40960 + (s) * 10240)
#define BLO_OFF(s) (61440 + (s) * 10240)
#define LOGITS_SMEM 81920

__global__ __launch_bounds__(256, 1) void logits_mma(const float* __restrict__ W,
                                                     float* __restrict__ out)
{
    extern __shared__ char smem[];
    const uint32_t sbase = smem_to_u32(smem);
    const int tid  = threadIdx.x;
    const int lane = tid & 31;
    const int w    = tid >> 5;
    const int wm   = w >> 2;   // 0..1
    const int wn   = w & 3;    // 0..3
    const int n0   = blockIdx.x * 128;
    const int m0   = blockIdx.y * 128;

    float d[4][4][4];
    #pragma unroll
    for (int i = 0; i < 4; i++)
        #pragma unroll
        for (int j = 0; j < 4; j++)
            #pragma unroll
            for (int q = 0; q < 4; q++) d[i][j][q] = 0.f;

    float4 breg[4];

    // --- A tiles via cp.async (bf16, pre-split) ---
    auto cpasync_A = [&](int c, int s) {
        const int k0 = c * 32;
        #pragma unroll
        for (int i = 0; i < 2; i++) {
            int idx = tid + i * 256;          // 0..511
            int row = idx >> 2;               // 0..127
            int ch  = idx & 3;                // 16B chunk
            const __nv_bfloat16* sh = &g_Ahi[(m0 + row) * DH + k0 + ch * 8];
            uint32_t dh = sbase + AHI_OFF(s) + row * ROWB + ch * 16;
            asm volatile("cp.async.ca.shared.global [%0], [%1], 16;" :: "r"(dh), "l"(sh));
            const __nv_bfloat16* sl = &g_Alo[(m0 + row) * DH + k0 + ch * 8];
            uint32_t dl = sbase + ALO_OFF(s) + row * ROWB + ch * 16;
            asm volatile("cp.async.ca.shared.global [%0], [%1], 16;" :: "r"(dl), "l"(sl));
        }
        asm volatile("cp.async.commit_group;" ::: "memory");
    };

    // --- B tile: LDG fp32 (128 rows x 32 k) ---
    auto ldg_B = [&](int c) {
        const int k0 = c * 32;
        #pragma unroll
        for (int i = 0; i < 4; i++) {
            int idx = tid + i * 256;          // 0..1023
            int row = idx >> 3;               // 0..127
            int col = (idx & 7) * 4;          // 0..28
            int vr = n0 + row;
            breg[i] = (vr < VOCAB)
                ? *reinterpret_cast<const float4*>(&W[(long)vr * DH + k0 + col])
                : make_float4(0.f, 0.f, 0.f, 0.f);
        }
    };

    // --- convert + store B hi/lo ---
    auto sts_B = [&](int s) {
        #pragma unroll
        for (int i = 0; i < 4; i++) {
            int idx = tid + i * 256;
            int row = idx >> 3;
            int col = (idx & 7) * 4;
            float4 v = breg[i];
            __nv_bfloat16 hx = __float2bfloat16(v.x), hy = __float2bfloat16(v.y);
            __nv_bfloat16 hz = __float2bfloat16(v.z), hw = __float2bfloat16(v.w);
            __nv_bfloat16 lx = __float2bfloat16(v.x - __bfloat162float(hx));
            __nv_bfloat16 ly = __float2bfloat16(v.y - __bfloat162float(hy));
            __nv_bfloat16 lz = __float2bfloat16(v.z - __bfloat162float(hz));
            __nv_bfloat16 lw = __float2bfloat16(v.w - __bfloat162float(hw));
            uint2 ph, pl;
            ph.x = pack_bf16x2(hx, hy); ph.y = pack_bf16x2(hz, hw);
            pl.x = pack_bf16x2(lx, ly); pl.y = pack_bf16x2(lz, lw);
            *reinterpret_cast<uint2*>(smem + BHI_OFF(s) + row * ROWB + col * 2) = ph;
            *reinterpret_cast<uint2*>(smem + BLO_OFF(s) + row * ROWB + col * 2) = pl;
        }
    };

    // --- compute one 32-K slab from stage s ---
    auto compute = [&](int s) {
        #pragma unroll
        for (int ks = 0; ks < 2; ks++) {
            uint32_t ah[4][4], al[4][4];
            #pragma unroll
            for (int mi = 0; mi < 4; mi++) {
                int row = wm * 64 + mi * 16 + (lane & 15);
                int kc  = ks * 32 + (lane >> 4) * 16;     // byte offset in 64B row
                ldsm4(ah[mi], sbase + AHI_OFF(s) + row * ROWB + kc);
                ldsm4(al[mi], sbase + ALO_OFF(s) + row * ROWB + kc);
            }
            uint32_t bh[4][2], bl[4][2];
            #pragma unroll
            for (int nb2 = 0; nb2 < 2; nb2++) {
                int g   = lane >> 3;
                int row = wn * 32 + nb2 * 16 + (g >> 1) * 8 + (lane & 7);
                int kc  = ks * 32 + (g & 1) * 16;
                ldsm4(&bh[nb2 * 2][0], sbase + BHI_OFF(s) + row * ROWB + kc);
                ldsm4(&bl[nb2 * 2][0], sbase + BLO_OFF(s) + row * ROWB + kc);
            }
            #pragma unroll
            for (int mi = 0; mi < 4; mi++)
                #pragma unroll
                for (int ni = 0; ni < 4; ni++) {
                    mma16816(d[mi][ni], ah[mi], bh[ni]);
                    mma16816(d[mi][ni], ah[mi], bl[ni]);
                    mma16816(d[mi][ni], al[mi], bh[ni]);
                }
        }
    };

    // prologue
    cpasync_A(0, 0);
    ldg_B(0);
    sts_B(0);
    asm volatile("cp.async.wait_group 0;" ::: "memory");
    __syncthreads();

    // main loop: 16 K-slabs, double-buffered
    #pragma unroll 1
    for (int c = 0; c < 16; c++) {
        int s = c & 1;
        if (c + 1 < 16) {
            cpasync_A(c + 1, 1 - s);
            ldg_B(c + 1);
        }
        compute(s);
        if (c + 1 < 16) {
            sts_B(1 - s);
            asm volatile("cp.async.wait_group 0;" ::: "memory");
        }
        __syncthreads();
    }

    // epilogue: direct stores (VOCAB odd -> scalar)
    const int g  = lane >> 2;
    const int i2 = (lane & 3) * 2;
    #pragma unroll
    for (int mi = 0; mi < 4; mi++) {
        int r0 = m0 + wm * 64 + mi * 16 + g;
        long rb0 = (long)r0 * VOCAB;
        long rb1 = (long)(r0 + 8) * VOCAB;
        #pragma unroll
        for (int ni = 0; ni < 4; ni++) {
            int col = n0 + wn * 32 + ni * 8 + i2;
            if (col < VOCAB) {
                out[rb0 + col] = d[mi][ni][0];
                out[rb1 + col] = d[mi][ni][2];
                if (col + 1 < VOCAB) {
                    out[rb0 + col + 1] = d[mi][ni][1];
                    out[rb1 + col + 1] = d[mi][ni][3];
                }
            }
        }
    }
}

// ---------------------------------------------------------------------------
extern "C" void kernel_launch(void* const* d_in, const int* in_sizes, int n_in,
                              void* d_out, int out_size)
{
    const float* hidden = (const float*)d_in[0];
    const int*   tids   = (const int*)  d_in[1];
    const float* ip_w   = (const float*)d_in[2];
    const float* ip_b   = (const float*)d_in[3];
    const float* w_ih0  = (const float*)d_in[4];
    const float* w_hh0  = (const float*)d_in[5];
    const float* b_ih0  = (const float*)d_in[6];
    const float* b_hh0  = (const float*)d_in[7];
    const float* w_ih1  = (const float*)d_in[8];
    const float* w_hh1  = (const float*)d_in[9];
    const float* b_ih1  = (const float*)d_in[10];
    const float* b_hh1  = (const float*)d_in[11];
    const float* embed  = (const float*)d_in[12];
    const float* out_w  = (const float*)d_in[13];
    float* out = (float*)d_out;

    cudaFuncSetAttribute(logits_mma, cudaFuncAttributeMaxDynamicSharedMemorySize, LOGITS_SMEM);

    // input projection -> h0 (both layer states), x = 0
    ip_gemm<<<dim3(8, 8), 256>>>(hidden, ip_w);
    ip_reduce<<<128, 256>>>(ip_b);

    for (int step = 0; step < NDRAFT; step++) {
        gates_gemm<<<dim3(48, 4), 256>>>(w_ih0, w_hh0, 0);
        gru_combine<<<128, 256>>>(b_ih0, b_hh0, 0, step);
        gates_gemm<<<dim3(48, 4), 256>>>(w_ih1, w_hh1, 1);
        gru_combine<<<128, 256>>>(b_ih1, b_hh1, 1, step);
        if (step < NDRAFT - 1) gather_x<<<128, 256>>>(embed, tids, step);
    }

    // convert h2 rows to bf16 hi/lo, then tensor-core vocab projection
    a_convert<<<(B_ * NDRAFT * DH + 255) / 256, 256>>>();
    logits_mma<<<dim3((VOCAB + 127) / 128, 2), 256, LOGITS_SMEM>>>(out_w, out);
}